// round 4
// baseline (speedup 1.0000x reference)
#include <cuda_runtime.h>
#include <cstdint>

// ---------------------------------------------------------------------------
// CliffordLinear as one dense GEMM via mma.sync tf32.
//   out[b, o*8+l] = sum_{i,k} X[b, i*8+k] * WtT[(o*8+l), (i*8+k)] + bias
//   WtT[(o,l),(i,k)] = cayley[k^l, k, l] * W[o, i, k^l]   (tf32-rounded)
// M=8192, N=2048, K=2048. A = x row-major [M,K]; B = WtT row-major [N,K].
// Fragment loads are vectorized by relabeling k within each 32-block so each
// thread's 8 needed k values (k === lc mod 4) are physically contiguous.
// ---------------------------------------------------------------------------

#define M_DIM 8192
#define N_DIM 2048
#define K_DIM 2048

__device__ float g_WtT[N_DIM * K_DIM];   // 16 MB static scratch (allowed)

__device__ __forceinline__ float tf32_rn(float x) {
    uint32_t r;
    asm("cvt.rna.tf32.f32 %0, %1;" : "=r"(r) : "f"(x));
    return __uint_as_float(r);
}

// ---------------------------------------------------------------------------
// Prologue: WtT[n][kk] = round_tf32( cayley[j,k,l] * W[o,i,j] ), j=k^l
// ---------------------------------------------------------------------------
__global__ void __launch_bounds__(1024) build_wt_kernel(const float* __restrict__ weight,
                                                        const float* __restrict__ cayley) {
    int t = blockIdx.x * blockDim.x + threadIdx.x;
    if (t >= N_DIM * K_DIM) return;
    int n  = t >> 11;        // o*8 + l
    int kk = t & 2047;       // i*8 + k
    int o = n >> 3,  l = n & 7;
    int i = kk >> 3, k = kk & 7;
    int j = k ^ l;
    g_WtT[t] = tf32_rn(cayley[(j * 8 + k) * 8 + l] * weight[(o * 256 + i) * 8 + j]);
}

// ---------------------------------------------------------------------------
// GEMM: BM=128, BN=128, BK=32, 3 stages, 256 threads (2x4 warps, 64x32/warp)
// ---------------------------------------------------------------------------
#define BM 128
#define BN 128
#define BK 32
#define BKP 36                       /* padded row stride in floats */
#define TILE_FLOATS (128 * BKP)      /* 4608 */
#define STAGE_BYTES (2 * TILE_FLOATS * 4)   /* 36864 */
#define NSTAGES 3
#define SMEM_TOTAL (NSTAGES * STAGE_BYTES)  /* 110592 */
#define NUM_ITERS (K_DIM / BK)       /* 64 */

__device__ __forceinline__ void mma_tf32(float& c0, float& c1, float& c2, float& c3,
                                         uint32_t a0, uint32_t a1, uint32_t a2, uint32_t a3,
                                         uint32_t b0, uint32_t b1) {
    asm volatile(
        "mma.sync.aligned.m16n8k8.row.col.f32.tf32.tf32.f32 "
        "{%0,%1,%2,%3}, {%4,%5,%6,%7}, {%8,%9}, {%0,%1,%2,%3};"
        : "+f"(c0), "+f"(c1), "+f"(c2), "+f"(c3)
        : "r"(a0), "r"(a1), "r"(a2), "r"(a3), "r"(b0), "r"(b1));
}

__global__ void __launch_bounds__(256, 1) clifford_mma_kernel(
    const float* __restrict__ A, const float* __restrict__ bias, float* __restrict__ C)
{
    extern __shared__ float smem[];
    const int tid  = threadIdx.x;
    const int wid  = tid >> 5;
    const int lane = tid & 31;
    const int wm = wid & 1;          // warp row (2 along M)
    const int wn = wid >> 1;         // warp col (4 along N)
    const int lr = lane >> 2;        // 0..7
    const int lc = lane & 3;         // 0..3

    const int block_m = blockIdx.y * BM;
    const int block_n = blockIdx.x * BN;

    const float* Abase = A     + (size_t)block_m * K_DIM;
    const float* Bbase = g_WtT + (size_t)block_n * K_DIM;

    uint32_t smem_u;
    asm("{ .reg .u64 t; cvta.to.shared.u64 t, %1; cvt.u32.u64 %0, t; }"
        : "=r"(smem_u) : "l"(smem));

#define LOAD_STAGE(s, k0) do {                                                      \
        uint32_t soff_ = smem_u + (uint32_t)(s) * STAGE_BYTES;                      \
        _Pragma("unroll")                                                           \
        for (int t_ = 0; t_ < 4; t_++) {                                            \
            int c_ = t_ * 256 + tid;                                                \
            int row_ = c_ >> 3, kq_ = c_ & 7;                                       \
            uint32_t so_ = soff_ + (uint32_t)(row_ * (BKP * 4) + kq_ * 16);         \
            const float* ga_ = Abase + (size_t)row_ * K_DIM + (k0) + kq_ * 4;       \
            asm volatile("cp.async.cg.shared.global [%0], [%1], 16;"                \
                         :: "r"(so_), "l"(ga_));                                    \
            const float* gb_ = Bbase + (size_t)row_ * K_DIM + (k0) + kq_ * 4;       \
            asm volatile("cp.async.cg.shared.global [%0], [%1], 16;"                \
                         :: "r"(so_ + TILE_FLOATS * 4), "l"(gb_));                  \
        }                                                                           \
    } while (0)

    float acc[4][4][4];
#pragma unroll
    for (int mi = 0; mi < 4; mi++)
#pragma unroll
        for (int ni = 0; ni < 4; ni++)
#pragma unroll
            for (int q = 0; q < 4; q++) acc[mi][ni][q] = 0.0f;

    LOAD_STAGE(0, 0);
    asm volatile("cp.async.commit_group;" ::: "memory");
    LOAD_STAGE(1, BK);
    asm volatile("cp.async.commit_group;" ::: "memory");

    for (int it = 0; it < NUM_ITERS; ++it) {
        asm volatile("cp.async.wait_group 1;" ::: "memory");
        __syncthreads();

        if (it + 2 < NUM_ITERS) LOAD_STAGE((it + 2) % NSTAGES, (it + 2) * BK);
        asm volatile("cp.async.commit_group;" ::: "memory");

        const float* As = smem + (size_t)(it % NSTAGES) * (2 * TILE_FLOATS);
        const float* Bs = As + TILE_FLOATS;

        // k relabeling: within this 32-k block, thread (lr,lc) consumes the 8
        // contiguous phys floats [8*lc, 8*lc+8).  phys 8*lc + s maps to mma
        // step ks = s/2, register slot a0/b0 (s even) or a2/b1 (s odd).
#pragma unroll
        for (int half = 0; half < 2; half++) {         // s in [4*half, 4*half+4)
            const int kbase = 8 * lc + 4 * half;
            float4 fa[4][2];
#pragma unroll
            for (int mi = 0; mi < 4; mi++) {
                int r = wm * 64 + mi * 16 + lr;
                fa[mi][0] = *reinterpret_cast<const float4*>(&As[(r    ) * BKP + kbase]);
                fa[mi][1] = *reinterpret_cast<const float4*>(&As[(r + 8) * BKP + kbase]);
            }
            float4 fb[4];
#pragma unroll
            for (int ni = 0; ni < 4; ni++) {
                int n = wn * 32 + ni * 8 + lr;
                fb[ni] = *reinterpret_cast<const float4*>(&Bs[n * BKP + kbase]);
            }
            // round A fragments to tf32 (B already rounded in prologue)
#pragma unroll
            for (int mi = 0; mi < 4; mi++)
#pragma unroll
                for (int rr = 0; rr < 2; rr++) {
                    fa[mi][rr].x = tf32_rn(fa[mi][rr].x);
                    fa[mi][rr].y = tf32_rn(fa[mi][rr].y);
                    fa[mi][rr].z = tf32_rn(fa[mi][rr].z);
                    fa[mi][rr].w = tf32_rn(fa[mi][rr].w);
                }
#pragma unroll
            for (int kss = 0; kss < 2; kss++) {        // s = 4*half + 2*kss + {0,1}
#pragma unroll
                for (int mi = 0; mi < 4; mi++) {
                    const float* pa0 = &fa[mi][0].x;
                    const float* pa1 = &fa[mi][1].x;
                    uint32_t a0 = __float_as_uint(pa0[2 * kss    ]);
                    uint32_t a2 = __float_as_uint(pa0[2 * kss + 1]);
                    uint32_t a1 = __float_as_uint(pa1[2 * kss    ]);
                    uint32_t a3 = __float_as_uint(pa1[2 * kss + 1]);
#pragma unroll
                    for (int ni = 0; ni < 4; ni++) {
                        const float* pb = &fb[ni].x;
                        uint32_t b0 = __float_as_uint(pb[2 * kss    ]);
                        uint32_t b1 = __float_as_uint(pb[2 * kss + 1]);
                        mma_tf32(acc[mi][ni][0], acc[mi][ni][1],
                                 acc[mi][ni][2], acc[mi][ni][3],
                                 a0, a1, a2, a3, b0, b1);
                    }
                }
            }
        }
    }

    // ---- epilogue: add bias, store ----
#pragma unroll
    for (int mi = 0; mi < 4; mi++) {
        int row0 = block_m + wm * 64 + mi * 16 + lr;
#pragma unroll
        for (int ni = 0; ni < 4; ni++) {
            int col = block_n + wn * 32 + ni * 8 + 2 * lc;
            float2 bv = *reinterpret_cast<const float2*>(bias + col);
            float2 o0, o1;
            o0.x = acc[mi][ni][0] + bv.x;
            o0.y = acc[mi][ni][1] + bv.y;
            o1.x = acc[mi][ni][2] + bv.x;
            o1.y = acc[mi][ni][3] + bv.y;
            *reinterpret_cast<float2*>(C + (size_t)row0 * N_DIM + col) = o0;
            *reinterpret_cast<float2*>(C + (size_t)(row0 + 8) * N_DIM + col) = o1;
        }
    }
}

// ---------------------------------------------------------------------------
// Launch.  Inputs: x, weight, bias, cayley (metadata order).
// ---------------------------------------------------------------------------
extern "C" void kernel_launch(void* const* d_in, const int* in_sizes, int n_in,
                              void* d_out, int out_size) {
    const float* x      = (const float*)d_in[0];   // [8192, 256, 8]
    const float* weight = (const float*)d_in[1];   // [256, 256, 8]
    const float* bias   = (const float*)d_in[2];   // [256, 8]
    const float* cayley = (const float*)d_in[3];   // [8, 8, 8]
    float* out = (float*)d_out;                    // [8192, 256, 8]
    (void)in_sizes; (void)n_in; (void)out_size;

    int total = N_DIM * K_DIM;
    build_wt_kernel<<<(total + 1023) / 1024, 1024>>>(weight, cayley);

    cudaFuncSetAttribute(clifford_mma_kernel,
                         cudaFuncAttributeMaxDynamicSharedMemorySize, SMEM_TOTAL);
    dim3 grid(N_DIM / BN, M_DIM / BM);   // (16, 64)
    clifford_mma_kernel<<<grid, 256, SMEM_TOTAL>>>(x, bias, out);
}

// round 5
// speedup vs baseline: 1.1786x; 1.1786x over previous
#include <cuda_runtime.h>
#include <cstdint>

// ---------------------------------------------------------------------------
// CliffordLinear as one dense GEMM via mma.sync tf32.
//   out[b, o*8+l] = sum_{i,k} X[b, i*8+k] * WtT[(o*8+l), (i*8+k)] + bias
//   WtT[(o,l),(i,k)] = cayley[k^l, k, l] * W[o, i, k^l]   (tf32-rounded)
// M=8192, N=2048, K=2048. A = x row-major [M,K]; B = WtT row-major [N,K].
// k within each 32-block is relabeled so each thread's 8 needed k values
// (k === lc mod 4) are physically contiguous -> all fragment loads LDS.128.
// ---------------------------------------------------------------------------

#define M_DIM 8192
#define N_DIM 2048
#define K_DIM 2048

__device__ float g_WtT[N_DIM * K_DIM];   // 16 MB static scratch (allowed)

__device__ __forceinline__ float tf32_rn(float x) {
    uint32_t r;
    asm("cvt.rna.tf32.f32 %0, %1;" : "=r"(r) : "f"(x));
    return __uint_as_float(r);
}

// ---------------------------------------------------------------------------
// Prologue: WtT[n][kk] = round_tf32( cayley[j,k,l] * W[o,i,j] ), j=k^l
// ---------------------------------------------------------------------------
__global__ void __launch_bounds__(1024) build_wt_kernel(const float* __restrict__ weight,
                                                        const float* __restrict__ cayley) {
    int t = blockIdx.x * blockDim.x + threadIdx.x;
    if (t >= N_DIM * K_DIM) return;
    int n  = t >> 11;        // o*8 + l
    int kk = t & 2047;       // i*8 + k
    int o = n >> 3,  l = n & 7;
    int i = kk >> 3, k = kk & 7;
    int j = k ^ l;
    g_WtT[t] = tf32_rn(cayley[(j * 8 + k) * 8 + l] * weight[(o * 256 + i) * 8 + j]);
}

// ---------------------------------------------------------------------------
// GEMM: BM=128, BN=128, BK=32, 3 stages, 256 threads (2x4 warps, 64x32/warp)
// ---------------------------------------------------------------------------
#define BM 128
#define BN 128
#define BK 32
#define BKP 36                       /* padded row stride in floats */
#define TILE_FLOATS (128 * BKP)      /* 4608 */
#define STAGE_BYTES (2 * TILE_FLOATS * 4)   /* 36864 */
#define NSTAGES 3
#define SMEM_TOTAL (NSTAGES * STAGE_BYTES)  /* 110592 */
#define NUM_ITERS (K_DIM / BK)       /* 64 */

__device__ __forceinline__ void mma_tf32(float& c0, float& c1, float& c2, float& c3,
                                         uint32_t a0, uint32_t a1, uint32_t a2, uint32_t a3,
                                         uint32_t b0, uint32_t b1) {
    asm volatile(
        "mma.sync.aligned.m16n8k8.row.col.f32.tf32.tf32.f32 "
        "{%0,%1,%2,%3}, {%4,%5,%6,%7}, {%8,%9}, {%0,%1,%2,%3};"
        : "+f"(c0), "+f"(c1), "+f"(c2), "+f"(c3)
        : "r"(a0), "r"(a1), "r"(a2), "r"(a3), "r"(b0), "r"(b1));
}

__global__ void __launch_bounds__(256, 2) clifford_mma_kernel(
    const float* __restrict__ A, const float* __restrict__ bias, float* __restrict__ C)
{
    extern __shared__ float smem[];
    const int tid  = threadIdx.x;
    const int wid  = tid >> 5;
    const int lane = tid & 31;
    const int wm = wid & 1;          // warp row (2 along M)
    const int wn = wid >> 1;         // warp col (4 along N)
    const int lr = lane >> 2;        // 0..7
    const int lc = lane & 3;         // 0..3

    const int block_m = blockIdx.y * BM;
    const int block_n = blockIdx.x * BN;

    const float* Abase = A     + (size_t)block_m * K_DIM;
    const float* Bbase = g_WtT + (size_t)block_n * K_DIM;

    uint32_t smem_u;
    asm("{ .reg .u64 t; cvta.to.shared.u64 t, %1; cvt.u32.u64 %0, t; }"
        : "=r"(smem_u) : "l"(smem));

#define LOAD_STAGE(s, k0) do {                                                      \
        uint32_t soff_ = smem_u + (uint32_t)(s) * STAGE_BYTES;                      \
        _Pragma("unroll")                                                           \
        for (int t_ = 0; t_ < 4; t_++) {                                            \
            int c_ = t_ * 256 + tid;                                                \
            int row_ = c_ >> 3, kq_ = c_ & 7;                                       \
            uint32_t so_ = soff_ + (uint32_t)(row_ * (BKP * 4) + kq_ * 16);         \
            const float* ga_ = Abase + (size_t)row_ * K_DIM + (k0) + kq_ * 4;       \
            asm volatile("cp.async.cg.shared.global [%0], [%1], 16;"                \
                         :: "r"(so_), "l"(ga_));                                    \
            const float* gb_ = Bbase + (size_t)row_ * K_DIM + (k0) + kq_ * 4;       \
            asm volatile("cp.async.cg.shared.global [%0], [%1], 16;"                \
                         :: "r"(so_ + TILE_FLOATS * 4), "l"(gb_));                  \
        }                                                                           \
    } while (0)

    float acc[4][4][4];
#pragma unroll
    for (int mi = 0; mi < 4; mi++)
#pragma unroll
        for (int ni = 0; ni < 4; ni++)
#pragma unroll
            for (int q = 0; q < 4; q++) acc[mi][ni][q] = 0.0f;

    LOAD_STAGE(0, 0);
    asm volatile("cp.async.commit_group;" ::: "memory");
    LOAD_STAGE(1, BK);
    asm volatile("cp.async.commit_group;" ::: "memory");

    // hoisted per-thread fragment offsets (floats)
    const int aOff = (wm * 64 + lr) * BKP + 8 * lc;
    const int bOff = (wn * 32 + lr) * BKP + 8 * lc;

    for (int it = 0; it < NUM_ITERS; ++it) {
        asm volatile("cp.async.wait_group 1;" ::: "memory");
        __syncthreads();

        if (it + 2 < NUM_ITERS) LOAD_STAGE((it + 2) % NSTAGES, (it + 2) * BK);
        asm volatile("cp.async.commit_group;" ::: "memory");

        const float* As = smem + (size_t)(it % NSTAGES) * (2 * TILE_FLOATS);
        const float* aP = As + aOff;
        const float* bP = As + TILE_FLOATS + bOff;

#pragma unroll
        for (int half = 0; half < 2; half++) {         // phys k: 8*lc + [4*half, 4*half+4)
            // stage B fragments for this half (16 regs)
            float4 fb[4];
#pragma unroll
            for (int ni = 0; ni < 4; ni++)
                fb[ni] = *reinterpret_cast<const float4*>(bP + ni * 8 * BKP + 4 * half);

#pragma unroll
            for (int mi = 0; mi < 4; mi++) {
                float4 fa0 = *reinterpret_cast<const float4*>(aP + (mi * 16    ) * BKP + 4 * half);
                float4 fa1 = *reinterpret_cast<const float4*>(aP + (mi * 16 + 8) * BKP + 4 * half);
                fa0.x = tf32_rn(fa0.x); fa0.y = tf32_rn(fa0.y);
                fa0.z = tf32_rn(fa0.z); fa0.w = tf32_rn(fa0.w);
                fa1.x = tf32_rn(fa1.x); fa1.y = tf32_rn(fa1.y);
                fa1.z = tf32_rn(fa1.z); fa1.w = tf32_rn(fa1.w);
                const float* pa0 = &fa0.x;
                const float* pa1 = &fa1.x;
#pragma unroll
                for (int kss = 0; kss < 2; kss++) {
                    uint32_t a0 = __float_as_uint(pa0[2 * kss    ]);
                    uint32_t a2 = __float_as_uint(pa0[2 * kss + 1]);
                    uint32_t a1 = __float_as_uint(pa1[2 * kss    ]);
                    uint32_t a3 = __float_as_uint(pa1[2 * kss + 1]);
#pragma unroll
                    for (int ni = 0; ni < 4; ni++) {
                        const float* pb = &fb[ni].x;
                        uint32_t b0 = __float_as_uint(pb[2 * kss    ]);
                        uint32_t b1 = __float_as_uint(pb[2 * kss + 1]);
                        mma_tf32(acc[mi][ni][0], acc[mi][ni][1],
                                 acc[mi][ni][2], acc[mi][ni][3],
                                 a0, a1, a2, a3, b0, b1);
                    }
                }
            }
        }
    }

    // ---- epilogue: add bias, store ----
#pragma unroll
    for (int mi = 0; mi < 4; mi++) {
        int row0 = block_m + wm * 64 + mi * 16 + lr;
#pragma unroll
        for (int ni = 0; ni < 4; ni++) {
            int col = block_n + wn * 32 + ni * 8 + 2 * lc;
            float2 bv = *reinterpret_cast<const float2*>(bias + col);
            float2 o0, o1;
            o0.x = acc[mi][ni][0] + bv.x;
            o0.y = acc[mi][ni][1] + bv.y;
            o1.x = acc[mi][ni][2] + bv.x;
            o1.y = acc[mi][ni][3] + bv.y;
            *reinterpret_cast<float2*>(C + (size_t)row0 * N_DIM + col) = o0;
            *reinterpret_cast<float2*>(C + (size_t)(row0 + 8) * N_DIM + col) = o1;
        }
    }
}

// ---------------------------------------------------------------------------
// Launch.  Inputs: x, weight, bias, cayley (metadata order).
// ---------------------------------------------------------------------------
extern "C" void kernel_launch(void* const* d_in, const int* in_sizes, int n_in,
                              void* d_out, int out_size) {
    const float* x      = (const float*)d_in[0];   // [8192, 256, 8]
    const float* weight = (const float*)d_in[1];   // [256, 256, 8]
    const float* bias   = (const float*)d_in[2];   // [256, 8]
    const float* cayley = (const float*)d_in[3];   // [8, 8, 8]
    float* out = (float*)d_out;                    // [8192, 256, 8]
    (void)in_sizes; (void)n_in; (void)out_size;

    int total = N_DIM * K_DIM;
    build_wt_kernel<<<(total + 1023) / 1024, 1024>>>(weight, cayley);

    cudaFuncSetAttribute(clifford_mma_kernel,
                         cudaFuncAttributeMaxDynamicSharedMemorySize, SMEM_TOTAL);
    dim3 grid(N_DIM / BN, M_DIM / BM);   // (16, 64)
    clifford_mma_kernel<<<grid, 256, SMEM_TOTAL>>>(x, bias, out);
}

// round 6
// speedup vs baseline: 1.2524x; 1.0626x over previous
#include <cuda_runtime.h>
#include <cstdint>

// ---------------------------------------------------------------------------
// CliffordLinear as one dense GEMM via mma.sync tf32.
//   out[b, o*8+l] = sum_{i,k} X[b, i*8+k] * WtT[(o*8+l), (i*8+k)] + bias
//   WtT[(o,l),(i,k)] = cayley[k^l, k, l] * W[o, i, k^l]   (tf32-rounded)
// M=8192, N=2048, K=2048.  A is pre-rounded to tf32 in a prologue pass so the
// GEMM mainloop issues no cvt at all; k within each 32-block is relabeled so
// each thread's 8 needed k values (k === lc mod 4) are contiguous -> LDS.128.
// ---------------------------------------------------------------------------

#define M_DIM 8192
#define N_DIM 2048
#define K_DIM 2048

__device__ float g_WtT[N_DIM * K_DIM];   // 16 MB: Cayley-transformed weights
__device__ float g_Ar [M_DIM * K_DIM];   // 64 MB: tf32-rounded activations

__device__ __forceinline__ float tf32_rn(float x) {
    uint32_t r;
    asm("cvt.rna.tf32.f32 %0, %1;" : "=r"(r) : "f"(x));
    return __uint_as_float(r);
}

// ---------------------------------------------------------------------------
// Prologue 1: WtT[n][kk] = round_tf32( cayley[j,k,l] * W[o,i,j] ), j=k^l
// ---------------------------------------------------------------------------
__global__ void __launch_bounds__(1024) build_wt_kernel(const float* __restrict__ weight,
                                                        const float* __restrict__ cayley) {
    int t = blockIdx.x * blockDim.x + threadIdx.x;
    if (t >= N_DIM * K_DIM) return;
    int n  = t >> 11;        // o*8 + l
    int kk = t & 2047;       // i*8 + k
    int o = n >> 3,  l = n & 7;
    int i = kk >> 3, k = kk & 7;
    int j = k ^ l;
    g_WtT[t] = tf32_rn(cayley[(j * 8 + k) * 8 + l] * weight[(o * 256 + i) * 8 + j]);
}

// ---------------------------------------------------------------------------
// Prologue 2: g_Ar = round_tf32(x), vectorized float4
// ---------------------------------------------------------------------------
__global__ void __launch_bounds__(1024) round_a_kernel(const float4* __restrict__ x4) {
    int t = blockIdx.x * blockDim.x + threadIdx.x;   // over 4M float4s
    float4 v = x4[t];
    v.x = tf32_rn(v.x); v.y = tf32_rn(v.y);
    v.z = tf32_rn(v.z); v.w = tf32_rn(v.w);
    reinterpret_cast<float4*>(g_Ar)[t] = v;
}

// ---------------------------------------------------------------------------
// GEMM: BM=128, BN=128, BK=32, 3 stages, 256 threads (2x4 warps, 64x32/warp)
// ---------------------------------------------------------------------------
#define BM 128
#define BN 128
#define BK 32
#define BKP 36                       /* padded row stride in floats */
#define TILE_FLOATS (128 * BKP)      /* 4608 */
#define STAGE_BYTES (2 * TILE_FLOATS * 4)   /* 36864 */
#define NSTAGES 3
#define SMEM_TOTAL (NSTAGES * STAGE_BYTES)  /* 110592 */
#define NUM_ITERS (K_DIM / BK)       /* 64 */

__device__ __forceinline__ void mma_tf32(float& c0, float& c1, float& c2, float& c3,
                                         uint32_t a0, uint32_t a1, uint32_t a2, uint32_t a3,
                                         uint32_t b0, uint32_t b1) {
    asm volatile(
        "mma.sync.aligned.m16n8k8.row.col.f32.tf32.tf32.f32 "
        "{%0,%1,%2,%3}, {%4,%5,%6,%7}, {%8,%9}, {%0,%1,%2,%3};"
        : "+f"(c0), "+f"(c1), "+f"(c2), "+f"(c3)
        : "r"(a0), "r"(a1), "r"(a2), "r"(a3), "r"(b0), "r"(b1));
}

__global__ void __launch_bounds__(256, 2) clifford_mma_kernel(
    const float* __restrict__ bias, float* __restrict__ C)
{
    extern __shared__ float smem[];
    const int tid  = threadIdx.x;
    const int wid  = tid >> 5;
    const int lane = tid & 31;
    const int wm = wid & 1;          // warp row (2 along M)
    const int wn = wid >> 1;         // warp col (4 along N)
    const int lr = lane >> 2;        // 0..7
    const int lc = lane & 3;         // 0..3

    const int block_m = blockIdx.y * BM;
    const int block_n = blockIdx.x * BN;

    uint32_t smem_u;
    asm("{ .reg .u64 t; cvta.to.shared.u64 t, %1; cvt.u32.u64 %0, t; }"
        : "=r"(smem_u) : "l"(smem));

    // ---- hoisted loader addressing: thread (r0, q0) copies 16B chunk q0 of
    // rows r0, r0+32, r0+64, r0+96 of both tiles ----
    const int r0 = tid >> 3;                     // 0..31
    const int q0 = tid & 7;                      // 0..7
    const uint32_t u0 = (uint32_t)(r0 * (BKP * 4) + q0 * 16);
    const float* gA = g_Ar  + (size_t)(block_m + r0) * K_DIM + q0 * 4;
    const float* gB = g_WtT + (size_t)(block_n + r0) * K_DIM + q0 * 4;

#define LOAD_STAGE(sbase, pA, pB) do {                                              \
        _Pragma("unroll")                                                           \
        for (int t_ = 0; t_ < 4; t_++) {                                            \
            asm volatile("cp.async.cg.shared.global [%0], [%1], 16;"                \
                :: "r"((sbase) + (uint32_t)(t_ * 32 * (BKP * 4))),                  \
                   "l"((pA) + (size_t)t_ * 32 * K_DIM));                            \
            asm volatile("cp.async.cg.shared.global [%0], [%1], 16;"                \
                :: "r"((sbase) + (uint32_t)(t_ * 32 * (BKP * 4) + TILE_FLOATS * 4)),\
                   "l"((pB) + (size_t)t_ * 32 * K_DIM));                            \
        }                                                                           \
    } while (0)

    float acc[4][4][4];
#pragma unroll
    for (int mi = 0; mi < 4; mi++)
#pragma unroll
        for (int ni = 0; ni < 4; ni++)
#pragma unroll
            for (int q = 0; q < 4; q++) acc[mi][ni][q] = 0.0f;

    // prefetch stages 0 (k=0) and 1 (k=32)
    LOAD_STAGE(smem_u + u0, gA, gB);
    asm volatile("cp.async.commit_group;" ::: "memory");
    LOAD_STAGE(smem_u + STAGE_BYTES + u0, gA + BK, gB + BK);
    asm volatile("cp.async.commit_group;" ::: "memory");

    const float* gA_run = gA + 2 * BK;           // next k to load
    const float* gB_run = gB + 2 * BK;

    // hoisted per-thread fragment offsets (floats)
    const int aOff = (wm * 64 + lr) * BKP + 8 * lc;
    const int bOff = TILE_FLOATS + (wn * 32 + lr) * BKP + 8 * lc;

    int sc = 0;   // compute stage
    int sl = 2;   // load stage

    for (int it = 0; it < NUM_ITERS; ++it) {
        asm volatile("cp.async.wait_group 1;" ::: "memory");
        __syncthreads();

        if (it + 2 < NUM_ITERS)
            LOAD_STAGE(smem_u + (uint32_t)sl * STAGE_BYTES + u0, gA_run, gB_run);
        asm volatile("cp.async.commit_group;" ::: "memory");
        gA_run += BK;
        gB_run += BK;

        const float* As = smem + sc * (2 * TILE_FLOATS);
        const float* aP = As + aOff;
        const float* bP = As + bOff;

#pragma unroll
        for (int half = 0; half < 2; half++) {   // phys k: 8*lc + [4*half, 4*half+4)
            float4 fb[4];
#pragma unroll
            for (int ni = 0; ni < 4; ni++)
                fb[ni] = *reinterpret_cast<const float4*>(bP + ni * 8 * BKP + 4 * half);

#pragma unroll
            for (int mi = 0; mi < 4; mi++) {
                float4 fa0 = *reinterpret_cast<const float4*>(aP + (mi * 16    ) * BKP + 4 * half);
                float4 fa1 = *reinterpret_cast<const float4*>(aP + (mi * 16 + 8) * BKP + 4 * half);
                const float* pa0 = &fa0.x;
                const float* pa1 = &fa1.x;
#pragma unroll
                for (int kss = 0; kss < 2; kss++) {
                    uint32_t a0 = __float_as_uint(pa0[2 * kss    ]);
                    uint32_t a2 = __float_as_uint(pa0[2 * kss + 1]);
                    uint32_t a1 = __float_as_uint(pa1[2 * kss    ]);
                    uint32_t a3 = __float_as_uint(pa1[2 * kss + 1]);
#pragma unroll
                    for (int ni = 0; ni < 4; ni++) {
                        const float* pb = &fb[ni].x;
                        uint32_t b0 = __float_as_uint(pb[2 * kss    ]);
                        uint32_t b1 = __float_as_uint(pb[2 * kss + 1]);
                        mma_tf32(acc[mi][ni][0], acc[mi][ni][1],
                                 acc[mi][ni][2], acc[mi][ni][3],
                                 a0, a1, a2, a3, b0, b1);
                    }
                }
            }
        }
        sc = (sc == NSTAGES - 1) ? 0 : sc + 1;
        sl = (sl == NSTAGES - 1) ? 0 : sl + 1;
    }

    // ---- epilogue: add bias, store ----
#pragma unroll
    for (int mi = 0; mi < 4; mi++) {
        int row0 = block_m + wm * 64 + mi * 16 + lr;
#pragma unroll
        for (int ni = 0; ni < 4; ni++) {
            int col = block_n + wn * 32 + ni * 8 + 2 * lc;
            float2 bv = *reinterpret_cast<const float2*>(bias + col);
            float2 o0, o1;
            o0.x = acc[mi][ni][0] + bv.x;
            o0.y = acc[mi][ni][1] + bv.y;
            o1.x = acc[mi][ni][2] + bv.x;
            o1.y = acc[mi][ni][3] + bv.y;
            *reinterpret_cast<float2*>(C + (size_t)row0 * N_DIM + col) = o0;
            *reinterpret_cast<float2*>(C + (size_t)(row0 + 8) * N_DIM + col) = o1;
        }
    }
}

// ---------------------------------------------------------------------------
// Launch.  Inputs: x, weight, bias, cayley (metadata order).
// ---------------------------------------------------------------------------
extern "C" void kernel_launch(void* const* d_in, const int* in_sizes, int n_in,
                              void* d_out, int out_size) {
    const float* x      = (const float*)d_in[0];   // [8192, 256, 8]
    const float* weight = (const float*)d_in[1];   // [256, 256, 8]
    const float* bias   = (const float*)d_in[2];   // [256, 8]
    const float* cayley = (const float*)d_in[3];   // [8, 8, 8]
    float* out = (float*)d_out;                    // [8192, 256, 8]
    (void)in_sizes; (void)n_in; (void)out_size;

    int totalW = N_DIM * K_DIM;
    build_wt_kernel<<<(totalW + 1023) / 1024, 1024>>>(weight, cayley);

    int totalA4 = M_DIM * K_DIM / 4;
    round_a_kernel<<<totalA4 / 1024, 1024>>>((const float4*)x);

    cudaFuncSetAttribute(clifford_mma_kernel,
                         cudaFuncAttributeMaxDynamicSharedMemorySize, SMEM_TOTAL);
    dim3 grid(N_DIM / BN, M_DIM / BM);   // (16, 64)
    clifford_mma_kernel<<<grid, 256, SMEM_TOTAL>>>(bias, out);
}

// round 7
// speedup vs baseline: 2.2946x; 1.8322x over previous
#include <cuda_runtime.h>
#include <cuda_fp16.h>
#include <cstdint>

// ---------------------------------------------------------------------------
// CliffordLinear as one dense GEMM via mma.sync m16n8k16 fp16 (fp32 accum).
//   out[b, o*8+l] = sum_{i,k} X[b, i*8+k] * WtT[(o*8+l), (i*8+k)] + bias
//   WtT[(o,l),(i,k)] = cayley[k^l, k, l] * W[o, i, k^l]
// M=8192, N=2048, K=2048.  A and B are converted to fp16 in prologue passes
// (fp16 mantissa == tf32 mantissa; data range is benign).  k within each
// 64-block is relabeled so each thread's 16 needed k-halfs are contiguous ->
// all fragment loads are LDS.128.
// ---------------------------------------------------------------------------

#define M_DIM 8192
#define N_DIM 2048
#define K_DIM 2048

__device__ __half g_Wh[N_DIM * K_DIM];   // 8 MB: fp16 Cayley-transformed weights
__device__ __half g_Ah[M_DIM * K_DIM];   // 32 MB: fp16 activations

// ---------------------------------------------------------------------------
// Prologue 1: Wh[n][kk] = fp16( cayley[j,k,l] * W[o,i,j] ), j=k^l
// ---------------------------------------------------------------------------
__global__ void __launch_bounds__(1024) build_wt_kernel(const float* __restrict__ weight,
                                                        const float* __restrict__ cayley) {
    int t = blockIdx.x * blockDim.x + threadIdx.x;
    if (t >= N_DIM * K_DIM) return;
    int n  = t >> 11;        // o*8 + l
    int kk = t & 2047;       // i*8 + k
    int o = n >> 3,  l = n & 7;
    int i = kk >> 3, k = kk & 7;
    int j = k ^ l;
    g_Wh[t] = __float2half_rn(cayley[(j * 8 + k) * 8 + l] * weight[(o * 256 + i) * 8 + j]);
}

// ---------------------------------------------------------------------------
// Prologue 2: g_Ah = fp16(x), 8 floats per thread
// ---------------------------------------------------------------------------
__global__ void __launch_bounds__(1024) convert_a_kernel(const float4* __restrict__ x4) {
    int t = blockIdx.x * blockDim.x + threadIdx.x;   // over pairs of float4
    float4 v0 = x4[2 * t];
    float4 v1 = x4[2 * t + 1];
    __half2 h[4];
    h[0] = __floats2half2_rn(v0.x, v0.y);
    h[1] = __floats2half2_rn(v0.z, v0.w);
    h[2] = __floats2half2_rn(v1.x, v1.y);
    h[3] = __floats2half2_rn(v1.z, v1.w);
    *reinterpret_cast<uint4*>(g_Ah + (size_t)t * 8) = *reinterpret_cast<uint4*>(h);
}

// ---------------------------------------------------------------------------
// GEMM: BM=128, BN=128, BK=64 halfs, 3 stages, 256 threads (2x4 warps,
// 64x32 per warp).  smem row = 64 halfs + 8 pad = 72 halfs = 144 B.
// ---------------------------------------------------------------------------
#define BM 128
#define BN 128
#define BK 64
#define BKP_H 72                           /* padded row stride in halfs */
#define TILE_BYTES (128 * BKP_H * 2)       /* 18432 */
#define STAGE_BYTES (2 * TILE_BYTES)       /* 36864 */
#define NSTAGES 3
#define SMEM_TOTAL (NSTAGES * STAGE_BYTES) /* 110592 */
#define NUM_ITERS (K_DIM / BK)             /* 32 */

__device__ __forceinline__ void mma_f16(float& c0, float& c1, float& c2, float& c3,
                                        uint32_t a0, uint32_t a1, uint32_t a2, uint32_t a3,
                                        uint32_t b0, uint32_t b1) {
    asm volatile(
        "mma.sync.aligned.m16n8k16.row.col.f32.f16.f16.f32 "
        "{%0,%1,%2,%3}, {%4,%5,%6,%7}, {%8,%9}, {%0,%1,%2,%3};"
        : "+f"(c0), "+f"(c1), "+f"(c2), "+f"(c3)
        : "r"(a0), "r"(a1), "r"(a2), "r"(a3), "r"(b0), "r"(b1));
}

__global__ void __launch_bounds__(256, 2) clifford_mma_kernel(
    const float* __restrict__ bias, float* __restrict__ C)
{
    extern __shared__ __half smem[];
    const int tid  = threadIdx.x;
    const int wid  = tid >> 5;
    const int lane = tid & 31;
    const int wm = wid & 1;          // warp row (2 along M)
    const int wn = wid >> 1;         // warp col (4 along N)
    const int lr = lane >> 2;        // 0..7
    const int lc = lane & 3;         // 0..3

    const int block_m = blockIdx.y * BM;
    const int block_n = blockIdx.x * BN;

    uint32_t smem_u;
    asm("{ .reg .u64 t; cvta.to.shared.u64 t, %1; cvt.u32.u64 %0, t; }"
        : "=r"(smem_u) : "l"(smem));

    // ---- loader addressing: thread (r0, q0) copies 16B chunk q0 (of 8) of
    // rows r0, r0+32, r0+64, r0+96 for both tiles ----
    const int r0 = tid >> 3;                     // 0..31
    const int q0 = tid & 7;                      // 0..7
    const uint32_t u0 = (uint32_t)(r0 * (BKP_H * 2) + q0 * 16);
    const __half* gA = g_Ah + (size_t)(block_m + r0) * K_DIM + q0 * 8;
    const __half* gB = g_Wh + (size_t)(block_n + r0) * K_DIM + q0 * 8;

#define LOAD_STAGE(sbase, pA, pB) do {                                               \
        _Pragma("unroll")                                                            \
        for (int t_ = 0; t_ < 4; t_++) {                                             \
            asm volatile("cp.async.cg.shared.global [%0], [%1], 16;"                 \
                :: "r"((sbase) + (uint32_t)(t_ * 32 * (BKP_H * 2))),                 \
                   "l"((pA) + (size_t)t_ * 32 * K_DIM));                             \
            asm volatile("cp.async.cg.shared.global [%0], [%1], 16;"                 \
                :: "r"((sbase) + (uint32_t)(t_ * 32 * (BKP_H * 2) + TILE_BYTES)),    \
                   "l"((pB) + (size_t)t_ * 32 * K_DIM));                             \
        }                                                                            \
    } while (0)

    float acc[4][4][4];
#pragma unroll
    for (int mi = 0; mi < 4; mi++)
#pragma unroll
        for (int ni = 0; ni < 4; ni++)
#pragma unroll
            for (int q = 0; q < 4; q++) acc[mi][ni][q] = 0.0f;

    LOAD_STAGE(smem_u + u0, gA, gB);
    asm volatile("cp.async.commit_group;" ::: "memory");
    LOAD_STAGE(smem_u + STAGE_BYTES + u0, gA + BK, gB + BK);
    asm volatile("cp.async.commit_group;" ::: "memory");

    const __half* gA_run = gA + 2 * BK;
    const __half* gB_run = gB + 2 * BK;

    // fragment offsets in halfs.  Thread consumes phys halfs [16*lc, 16*lc+16)
    // of its rows; chunk q (LDS.128 = 8 halfs) covers mma k-steps {2q, 2q+1}:
    //   v.x = a0/b0 of step 2q, v.y = a2/b1 of step 2q,
    //   v.z = a0/b0 of step 2q+1, v.w = a2/b1 of step 2q+1.
    const int aOff = (wm * 64 + lr) * BKP_H + 16 * lc;
    const int bOff = 128 * BKP_H + (wn * 32 + lr) * BKP_H + 16 * lc;

    int sc = 0;   // compute stage
    int sl = 2;   // load stage

    for (int it = 0; it < NUM_ITERS; ++it) {
        asm volatile("cp.async.wait_group 1;" ::: "memory");
        __syncthreads();

        if (it + 2 < NUM_ITERS)
            LOAD_STAGE(smem_u + (uint32_t)sl * STAGE_BYTES + u0, gA_run, gB_run);
        asm volatile("cp.async.commit_group;" ::: "memory");
        gA_run += BK;
        gB_run += BK;

        const __half* As = smem + sc * (STAGE_BYTES / 2);
        const __half* aP = As + aOff;
        const __half* bP = As + bOff;

#pragma unroll
        for (int q = 0; q < 2; q++) {            // mma k-steps {2q, 2q+1}
            uint4 fb[4];
#pragma unroll
            for (int ni = 0; ni < 4; ni++)
                fb[ni] = *reinterpret_cast<const uint4*>(bP + ni * 8 * BKP_H + 8 * q);

#pragma unroll
            for (int mi = 0; mi < 4; mi++) {
                uint4 fa0 = *reinterpret_cast<const uint4*>(aP + (mi * 16    ) * BKP_H + 8 * q);
                uint4 fa1 = *reinterpret_cast<const uint4*>(aP + (mi * 16 + 8) * BKP_H + 8 * q);
                const uint32_t* pa0 = &fa0.x;
                const uint32_t* pa1 = &fa1.x;
#pragma unroll
                for (int kk = 0; kk < 2; kk++) {
                    uint32_t a0 = pa0[2 * kk    ];
                    uint32_t a2 = pa0[2 * kk + 1];
                    uint32_t a1 = pa1[2 * kk    ];
                    uint32_t a3 = pa1[2 * kk + 1];
#pragma unroll
                    for (int ni = 0; ni < 4; ni++) {
                        const uint32_t* pb = &fb[ni].x;
                        mma_f16(acc[mi][ni][0], acc[mi][ni][1],
                                acc[mi][ni][2], acc[mi][ni][3],
                                a0, a1, a2, a3, pb[2 * kk], pb[2 * kk + 1]);
                    }
                }
            }
        }
        sc = (sc == NSTAGES - 1) ? 0 : sc + 1;
        sl = (sl == NSTAGES - 1) ? 0 : sl + 1;
    }

    // ---- epilogue: add bias, store ----
#pragma unroll
    for (int mi = 0; mi < 4; mi++) {
        int row0 = block_m + wm * 64 + mi * 16 + lr;
#pragma unroll
        for (int ni = 0; ni < 4; ni++) {
            int col = block_n + wn * 32 + ni * 8 + 2 * lc;
            float2 bv = *reinterpret_cast<const float2*>(bias + col);
            float2 o0, o1;
            o0.x = acc[mi][ni][0] + bv.x;
            o0.y = acc[mi][ni][1] + bv.y;
            o1.x = acc[mi][ni][2] + bv.x;
            o1.y = acc[mi][ni][3] + bv.y;
            *reinterpret_cast<float2*>(C + (size_t)row0 * N_DIM + col) = o0;
            *reinterpret_cast<float2*>(C + (size_t)(row0 + 8) * N_DIM + col) = o1;
        }
    }
}

// ---------------------------------------------------------------------------
// Launch.  Inputs: x, weight, bias, cayley (metadata order).
// ---------------------------------------------------------------------------
extern "C" void kernel_launch(void* const* d_in, const int* in_sizes, int n_in,
                              void* d_out, int out_size) {
    const float* x      = (const float*)d_in[0];   // [8192, 256, 8]
    const float* weight = (const float*)d_in[1];   // [256, 256, 8]
    const float* bias   = (const float*)d_in[2];   // [256, 8]
    const float* cayley = (const float*)d_in[3];   // [8, 8, 8]
    float* out = (float*)d_out;                    // [8192, 256, 8]
    (void)in_sizes; (void)n_in; (void)out_size;

    int totalW = N_DIM * K_DIM;
    build_wt_kernel<<<(totalW + 1023) / 1024, 1024>>>(weight, cayley);

    int totalA8 = M_DIM * K_DIM / 8;
    convert_a_kernel<<<totalA8 / 1024, 1024>>>((const float4*)x);

    cudaFuncSetAttribute(clifford_mma_kernel,
                         cudaFuncAttributeMaxDynamicSharedMemorySize, SMEM_TOTAL);
    dim3 grid(N_DIM / BN, M_DIM / BM);   // (16, 64)
    clifford_mma_kernel<<<grid, 256, SMEM_TOTAL>>>(bias, out);
}

// round 8
// speedup vs baseline: 3.5711x; 1.5563x over previous
#include <cuda_runtime.h>
#include <cuda_fp16.h>
#include <cstdint>

// ---------------------------------------------------------------------------
// CliffordLinear via the isomorphism Cl(3,0) ~= M2(C)  (e1,e2,e3 -> Pauli).
// Geometric product -> 2x2 complex matmul: HALVES the GEMM MACs vs the dense
// blade embedding (32 vs 64 real MACs per product).
//
// Blade coeffs a[0..7] (bitmask: 3=e12, 5=e13, 6=e23, 7=e123) map to
//   m00 = (a0+a4) + i(a3+a7)     m01 = (a1-a5) + i(-a2+a6)
//   m10 = (a1+a5) + i(a2+a6)     m11 = (a0-a4) + i(-a3+a7)
// and out = W.X (matrix product), recovered by the inverse (+- halves).
//
// One real GEMM: A[16384 x 1024] fp16, row 2b+c:
//   k=2i+cc       -> Re Xm[b,i](cc,c)
//   k=512+2i+cc   -> Im Xm[b,i](cc,c)
// B[1024 x 1024] fp16, row n=4o+2s+r:
//   s=0: k<512 -> +.5*Re Wm[o,i](r,cc),  k>=512 -> -.5*Im Wm(r,cc)
//   s=1: k<512 -> +.5*Im Wm(r,cc),       k>=512 -> +.5*Re Wm(r,cc)
// Out[2b+c, 4o+2s+r] = .5*(s?Im:Re) (Wm.Xm)(r,c); blades rebuilt in epilogue.
// ---------------------------------------------------------------------------

#define B_DIM 8192
#define CIN  256
#define COUT 256
#define M_GEMM 16384
#define N_GEMM 1024
#define K_GEMM 1024

__device__ __half g_Ah[M_GEMM * K_GEMM];   // 32 MB
__device__ __half g_Bh[N_GEMM * K_GEMM];   // 2 MB

// ---------------------------------------------------------------------------
// Prologue 1: x -> A matrix.  One thread per (b,i).
// ---------------------------------------------------------------------------
__global__ void __launch_bounds__(1024) a_transform_kernel(const float4* __restrict__ x4) {
    int t = blockIdx.x * 1024 + threadIdx.x;       // 0 .. B*CIN-1
    float4 v0 = x4[2 * t];                          // x0..x3
    float4 v1 = x4[2 * t + 1];                      // x4..x7
    int b = t >> 8, i = t & 255;
    __half2* A = reinterpret_cast<__half2*>(g_Ah);
    // row 2b   (c=0):  Re(m00),Re(m10) | Im(m00),Im(m10)
    A[(2 * b    ) * 512 +       i] = __floats2half2_rn(v0.x + v1.x, v0.y + v1.y);
    A[(2 * b    ) * 512 + 256 + i] = __floats2half2_rn(v0.w + v1.w, v0.z + v1.z);
    // row 2b+1 (c=1):  Re(m01),Re(m11) | Im(m01),Im(m11)
    A[(2 * b + 1) * 512 +       i] = __floats2half2_rn(v0.y - v1.y, v0.x - v1.x);
    A[(2 * b + 1) * 512 + 256 + i] = __floats2half2_rn(v1.z - v0.z, v1.w - v0.w);
}

// ---------------------------------------------------------------------------
// Prologue 2: weight -> B matrix.  One thread per (o,i).
// ---------------------------------------------------------------------------
__global__ void __launch_bounds__(1024) b_transform_kernel(const float* __restrict__ w) {
    int t = blockIdx.x * 1024 + threadIdx.x;       // 0 .. COUT*CIN-1
    int o = t >> 8, i = t & 255;
    const float* p = w + (size_t)t * 8;
    float w0 = p[0], w1 = p[1], w2 = p[2], w3 = p[3];
    float w4 = p[4], w5 = p[5], w6 = p[6], w7 = p[7];
    float Rm00 = .5f * (w0 + w4), Rm01 = .5f * (w1 - w5);
    float Rm10 = .5f * (w1 + w5), Rm11 = .5f * (w0 - w4);
    float Im00 = .5f * (w3 + w7), Im01 = .5f * (w6 - w2);
    float Im10 = .5f * (w2 + w6), Im11 = .5f * (w7 - w3);
    __half2* Bm = reinterpret_cast<__half2*>(g_Bh);
    int n0 = 4 * o;
    Bm[(n0    ) * 512 +       i] = __floats2half2_rn( Rm00,  Rm01);
    Bm[(n0    ) * 512 + 256 + i] = __floats2half2_rn(-Im00, -Im01);
    Bm[(n0 + 1) * 512 +       i] = __floats2half2_rn( Rm10,  Rm11);
    Bm[(n0 + 1) * 512 + 256 + i] = __floats2half2_rn(-Im10, -Im11);
    Bm[(n0 + 2) * 512 +       i] = __floats2half2_rn( Im00,  Im01);
    Bm[(n0 + 2) * 512 + 256 + i] = __floats2half2_rn( Rm00,  Rm01);
    Bm[(n0 + 3) * 512 +       i] = __floats2half2_rn( Im10,  Im11);
    Bm[(n0 + 3) * 512 + 256 + i] = __floats2half2_rn( Rm10,  Rm11);
}

// ---------------------------------------------------------------------------
// GEMM: BM=128, BN=128, BK=64 halfs, 3 stages, 256 threads (2x4 warps,
// 64x32 per warp).  smem row = 64 halfs + 8 pad = 72 halfs = 144 B.
// ---------------------------------------------------------------------------
#define BKP_H 72
#define TILE_BYTES (128 * BKP_H * 2)       /* 18432 */
#define STAGE_BYTES (2 * TILE_BYTES)       /* 36864 */
#define NSTAGES 3
#define SMEM_TOTAL (NSTAGES * STAGE_BYTES) /* 110592 */
#define NUM_ITERS (K_GEMM / 64)            /* 16 */

__device__ __forceinline__ void mma_f16(float& c0, float& c1, float& c2, float& c3,
                                        uint32_t a0, uint32_t a1, uint32_t a2, uint32_t a3,
                                        uint32_t b0, uint32_t b1) {
    asm volatile(
        "mma.sync.aligned.m16n8k16.row.col.f32.f16.f16.f32 "
        "{%0,%1,%2,%3}, {%4,%5,%6,%7}, {%8,%9}, {%0,%1,%2,%3};"
        : "+f"(c0), "+f"(c1), "+f"(c2), "+f"(c3)
        : "r"(a0), "r"(a1), "r"(a2), "r"(a3), "r"(b0), "r"(b1));
}

__global__ void __launch_bounds__(256, 2) clifford_mma_kernel(
    const float* __restrict__ bias, float* __restrict__ C)
{
    extern __shared__ __half smem[];
    const int tid  = threadIdx.x;
    const int wid  = tid >> 5;
    const int lane = tid & 31;
    const int wm = wid & 1;          // warp row (2 along M)
    const int wn = wid >> 1;         // warp col (4 along N)
    const int lr = lane >> 2;        // 0..7
    const int lc = lane & 3;         // 0..3

    const int block_m = blockIdx.y * 128;
    const int block_n = blockIdx.x * 128;

    uint32_t smem_u;
    asm("{ .reg .u64 t; cvta.to.shared.u64 t, %1; cvt.u32.u64 %0, t; }"
        : "=r"(smem_u) : "l"(smem));

    const int r0 = tid >> 3;                     // 0..31
    const int q0 = tid & 7;                      // 0..7
    const uint32_t u0 = (uint32_t)(r0 * (BKP_H * 2) + q0 * 16);
    const __half* gA = g_Ah + (size_t)(block_m + r0) * K_GEMM + q0 * 8;
    const __half* gB = g_Bh + (size_t)(block_n + r0) * K_GEMM + q0 * 8;

#define LOAD_STAGE(sbase, pA, pB) do {                                               \
        _Pragma("unroll")                                                            \
        for (int t_ = 0; t_ < 4; t_++) {                                             \
            asm volatile("cp.async.cg.shared.global [%0], [%1], 16;"                 \
                :: "r"((sbase) + (uint32_t)(t_ * 32 * (BKP_H * 2))),                 \
                   "l"((pA) + (size_t)t_ * 32 * K_GEMM));                            \
            asm volatile("cp.async.cg.shared.global [%0], [%1], 16;"                 \
                :: "r"((sbase) + (uint32_t)(t_ * 32 * (BKP_H * 2) + TILE_BYTES)),    \
                   "l"((pB) + (size_t)t_ * 32 * K_GEMM));                            \
        }                                                                            \
    } while (0)

    float acc[4][4][4];
#pragma unroll
    for (int mi = 0; mi < 4; mi++)
#pragma unroll
        for (int ni = 0; ni < 4; ni++)
#pragma unroll
            for (int q = 0; q < 4; q++) acc[mi][ni][q] = 0.0f;

    LOAD_STAGE(smem_u + u0, gA, gB);
    asm volatile("cp.async.commit_group;" ::: "memory");
    LOAD_STAGE(smem_u + STAGE_BYTES + u0, gA + 64, gB + 64);
    asm volatile("cp.async.commit_group;" ::: "memory");

    const __half* gA_run = gA + 128;
    const __half* gB_run = gB + 128;

    const int aOff = (wm * 64 + lr) * BKP_H + 16 * lc;
    const int bOff = 128 * BKP_H + (wn * 32 + lr) * BKP_H + 16 * lc;

    int sc = 0, sl = 2;

    for (int it = 0; it < NUM_ITERS; ++it) {
        asm volatile("cp.async.wait_group 1;" ::: "memory");
        __syncthreads();

        if (it + 2 < NUM_ITERS)
            LOAD_STAGE(smem_u + (uint32_t)sl * STAGE_BYTES + u0, gA_run, gB_run);
        asm volatile("cp.async.commit_group;" ::: "memory");
        gA_run += 64;
        gB_run += 64;

        const __half* As = smem + sc * (STAGE_BYTES / 2);
        const __half* aP = As + aOff;
        const __half* bP = As + bOff;

#pragma unroll
        for (int q = 0; q < 2; q++) {
            uint4 fb[4];
#pragma unroll
            for (int ni = 0; ni < 4; ni++)
                fb[ni] = *reinterpret_cast<const uint4*>(bP + ni * 8 * BKP_H + 8 * q);

#pragma unroll
            for (int mi = 0; mi < 4; mi++) {
                uint4 fa0 = *reinterpret_cast<const uint4*>(aP + (mi * 16    ) * BKP_H + 8 * q);
                uint4 fa1 = *reinterpret_cast<const uint4*>(aP + (mi * 16 + 8) * BKP_H + 8 * q);
                const uint32_t* pa0 = &fa0.x;
                const uint32_t* pa1 = &fa1.x;
#pragma unroll
                for (int kk = 0; kk < 2; kk++) {
                    uint32_t a0 = pa0[2 * kk    ];
                    uint32_t a2 = pa0[2 * kk + 1];
                    uint32_t a1 = pa1[2 * kk    ];
                    uint32_t a3 = pa1[2 * kk + 1];
#pragma unroll
                    for (int ni = 0; ni < 4; ni++) {
                        const uint32_t* pb = &fb[ni].x;
                        mma_f16(acc[mi][ni][0], acc[mi][ni][1],
                                acc[mi][ni][2], acc[mi][ni][3],
                                a0, a1, a2, a3, pb[2 * kk], pb[2 * kk + 1]);
                    }
                }
            }
        }
        sc = (sc == NSTAGES - 1) ? 0 : sc + 1;
        sl = (sl == NSTAGES - 1) ? 0 : sl + 1;
    }

    // ---- epilogue: stage warp tile to smem, rebuild blades, +bias, store ----
    asm volatile("cp.async.wait_group 0;" ::: "memory");
    __syncthreads();   // smem stages free for reuse

#define EPS 34   /* epilogue row stride (floats), even -> float2-aligned */
    float* ep = reinterpret_cast<float*>(smem) + wid * (64 * EPS);
#pragma unroll
    for (int mi = 0; mi < 4; mi++)
#pragma unroll
        for (int ni = 0; ni < 4; ni++) {
            float2 v0 = make_float2(acc[mi][ni][0], acc[mi][ni][1]);
            float2 v1 = make_float2(acc[mi][ni][2], acc[mi][ni][3]);
            *reinterpret_cast<float2*>(ep + (mi * 16 + lr    ) * EPS + ni * 8 + 2 * lc) = v0;
            *reinterpret_cast<float2*>(ep + (mi * 16 + lr + 8) * EPS + ni * 8 + 2 * lc) = v1;
        }
    __syncwarp();

    // lane = local b; warp tile: rows 64 = 32 b x (c=0,1); cols 32 = 8 o x 4
    const int b_glob = block_m / 2 + wm * 32 + lane;
    const int o0 = block_n / 4 + wn * 8;
    float* Crow = C + (size_t)b_glob * (COUT * 8);
    const float* rowA = ep + (2 * lane) * EPS;       // c = 0
    const float* rowB = rowA + EPS;                  // c = 1
#pragma unroll
    for (int ol = 0; ol < 8; ol++) {
        float A0 = rowA[4 * ol], A1 = rowA[4 * ol + 1], A2 = rowA[4 * ol + 2], A3 = rowA[4 * ol + 3];
        float B0 = rowB[4 * ol], B1 = rowB[4 * ol + 1], B2 = rowB[4 * ol + 2], B3 = rowB[4 * ol + 3];
        int o = o0 + ol;
        float4 bv0 = *reinterpret_cast<const float4*>(bias + o * 8);
        float4 bv1 = *reinterpret_cast<const float4*>(bias + o * 8 + 4);
        float4 u, v;
        u.x = A0 + B1 + bv0.x;     // a0
        u.y = B0 + A1 + bv0.y;     // a1 (e1)
        u.z = A3 - B2 + bv0.z;     // a2 (e2)
        u.w = A2 - B3 + bv0.w;     // a3 (e12)
        v.x = A0 - B1 + bv1.x;     // a4 (e3)
        v.y = A1 - B0 + bv1.y;     // a5 (e13)
        v.z = B2 + A3 + bv1.z;     // a6 (e23)
        v.w = A2 + B3 + bv1.w;     // a7 (e123)
        *reinterpret_cast<float4*>(Crow + o * 8    ) = u;
        *reinterpret_cast<float4*>(Crow + o * 8 + 4) = v;
    }
}

// ---------------------------------------------------------------------------
// Launch.  Inputs: x, weight, bias, cayley (metadata order).
// ---------------------------------------------------------------------------
extern "C" void kernel_launch(void* const* d_in, const int* in_sizes, int n_in,
                              void* d_out, int out_size) {
    const float* x      = (const float*)d_in[0];   // [8192, 256, 8]
    const float* weight = (const float*)d_in[1];   // [256, 256, 8]
    const float* bias   = (const float*)d_in[2];   // [256, 8]
    float* out = (float*)d_out;                    // [8192, 256, 8]
    (void)in_sizes; (void)n_in; (void)out_size;

    a_transform_kernel<<<(B_DIM * CIN) / 1024, 1024>>>((const float4*)x);
    b_transform_kernel<<<(COUT * CIN) / 1024, 1024>>>(weight);

    cudaFuncSetAttribute(clifford_mma_kernel,
                         cudaFuncAttributeMaxDynamicSharedMemorySize, SMEM_TOTAL);
    dim3 grid(N_GEMM / 128, M_GEMM / 128);   // (8, 128)
    clifford_mma_kernel<<<grid, 256, SMEM_TOTAL>>>(bias, out);
}